// round 4
// baseline (speedup 1.0000x reference)
#include <cuda_runtime.h>
#include <cuda_bf16.h>

#define NF      2048
#define NROWS   8192
#define RCHUNKS 512
#define RPC     (NROWS / RCHUNKS)   // 16 rows per chunk

// Scratch (allocation-free): partial sums/sumsqs + final stats
__device__ float g_psum[RCHUNKS * NF];   // 4 MiB
__device__ float g_psq [RCHUNKS * NF];   // 4 MiB
__device__ float g_mean[NF];
__device__ float g_istd[NF];

// ---------------------------------------------------------------------------
// Pass 1: (1024 cols) x (16 rows) partial sum/sumsq per block, grid (2,512).
// Loads batched 8-deep into a register buffer to force MLP ~8 per thread
// (previous version compiled to 31 regs -> only ~2 loads in flight).
// __launch_bounds__(256,4): allow ~64 regs, still 32 warps/SM.
// ---------------------------------------------------------------------------
__global__ void __launch_bounds__(256, 4) k_partial(const float* __restrict__ x) {
    const int col   = (blockIdx.x * 256 + threadIdx.x) * 4;
    const int chunk = blockIdx.y;
    const float4* xp = reinterpret_cast<const float4*>(
        x + (size_t)chunk * RPC * NF + col);

    float4 s = make_float4(0.f, 0.f, 0.f, 0.f);
    float4 q = make_float4(0.f, 0.f, 0.f, 0.f);

    #pragma unroll
    for (int b = 0; b < RPC / 8; ++b) {
        float4 buf[8];
        #pragma unroll
        for (int r = 0; r < 8; ++r)
            buf[r] = xp[(size_t)(b * 8 + r) * (NF / 4)];
        #pragma unroll
        for (int r = 0; r < 8; ++r) {
            const float4 v = buf[r];
            s.x += v.x;       s.y += v.y;       s.z += v.z;       s.w += v.w;
            q.x += v.x * v.x; q.y += v.y * v.y; q.z += v.z * v.z; q.w += v.w * v.w;
        }
    }
    *reinterpret_cast<float4*>(g_psum + chunk * NF + col) = s;
    *reinterpret_cast<float4*>(g_psq  + chunk * NF + col) = q;
}

// ---------------------------------------------------------------------------
// Pass 2: 128 blocks x 256 threads. Each block owns 16 columns; 16 threads
// per column each sum 32 partials (consecutive threads -> consecutive cols,
// 64B segments; partials are L2-resident). Fixed-order shared combine.
// var = (sumsq - N*mean^2)/(N-1)  (ddof=1, matches sequential Welford).
// ---------------------------------------------------------------------------
__global__ void __launch_bounds__(256) k_finish() {
    __shared__ float ssum[256];
    __shared__ float ssq [256];
    const int t  = threadIdx.x;
    const int cl = t & 15;                      // column within block
    const int j  = t >> 4;                      // partial-segment index [0,16)
    const int c  = blockIdx.x * 16 + cl;        // global column

    float s = 0.f, q = 0.f;
    #pragma unroll 8
    for (int k = j * 32; k < j * 32 + 32; ++k) {
        s += g_psum[k * NF + c];
        q += g_psq [k * NF + c];
    }
    ssum[t] = s;
    ssq [t] = q;
    __syncthreads();

    if (j == 0) {
        double S = 0.0, Q = 0.0;
        #pragma unroll
        for (int jj = 0; jj < 16; ++jj) {
            S += (double)ssum[jj * 16 + cl];
            Q += (double)ssq [jj * 16 + cl];
        }
        const double mean = S / (double)NROWS;
        const double var  = (Q - S * mean) / (double)(NROWS - 1);
        g_mean[c] = (float)mean;
        g_istd[c] = (float)(1.0 / sqrt(var + 1e-6));
    }
}

// ---------------------------------------------------------------------------
// Pass 3: out = (x - mean[col]) * istd[col]. ILP=2: each thread handles two
// block-strided float4s (both fully coalesced). x should hit L2 (populated by
// pass 1); __ldcs/__stcs = evict-first so the write stream doesn't evict
// not-yet-read x lines.
// ---------------------------------------------------------------------------
__global__ void __launch_bounds__(256) k_norm(const float* __restrict__ x,
                                              float* __restrict__ out) {
    const size_t base = (size_t)blockIdx.x * 512 + threadIdx.x;  // float4 idx
    const int col0 = (int)((base * 4) & (NF - 1));
    const int col1 = (col0 + 1024) & (NF - 1);   // base+256 float4s = +1024 cols

    float4 v0 = __ldcs(reinterpret_cast<const float4*>(x) + base);
    float4 v1 = __ldcs(reinterpret_cast<const float4*>(x) + base + 256);
    float4 m0 = *reinterpret_cast<const float4*>(g_mean + col0);
    float4 t0 = *reinterpret_cast<const float4*>(g_istd + col0);
    float4 m1 = *reinterpret_cast<const float4*>(g_mean + col1);
    float4 t1 = *reinterpret_cast<const float4*>(g_istd + col1);

    float4 o0, o1;
    o0.x = (v0.x - m0.x) * t0.x;  o0.y = (v0.y - m0.y) * t0.y;
    o0.z = (v0.z - m0.z) * t0.z;  o0.w = (v0.w - m0.w) * t0.w;
    o1.x = (v1.x - m1.x) * t1.x;  o1.y = (v1.y - m1.y) * t1.y;
    o1.z = (v1.z - m1.z) * t1.z;  o1.w = (v1.w - m1.w) * t1.w;

    __stcs(reinterpret_cast<float4*>(out) + base,       o0);
    __stcs(reinterpret_cast<float4*>(out) + base + 256, o1);
}

extern "C" void kernel_launch(void* const* d_in, const int* in_sizes, int n_in,
                              void* d_out, int out_size) {
    const float* x = (const float*)d_in[0];   // [8192, 2048] fp32
    float* out = (float*)d_out;               // [8192, 2048] fp32

    k_partial<<<dim3(NF / 1024, RCHUNKS), 256>>>(x);
    k_finish <<<NF / 16, 256>>>();
    k_norm   <<<(NROWS * (NF / 4)) / 512, 256>>>(x, out);
}